// round 2
// baseline (speedup 1.0000x reference)
#include <cuda_runtime.h>

// Problem constants
#define DIMC   512
#define HEADS  8
#define HD     64
#define NTOK   64
#define BATCH  2048
#define SCALE_Q 0.125f   // 64^-0.5
#define PAD    68        // 64 + 4 : float4-aligned, bank-conflict-free transposed tiles

// Scratch for attention output in [B, N, DIM] layout (256 MB, static device array
// per harness rules: no cudaMalloc anywhere).
__device__ float g_x[(size_t)BATCH * NTOK * DIMC];

// ---------------------------------------------------------------------------
// 64x64x(512) projection tile: acc[4][4] += X(64x512 slice) @ W_rows(64x512)^T
// X tile and W tile are staged transposed in SMEM ([k][row]) so the inner loop
// does two float4 LDS per k. All threads call (contains __syncthreads).
// ---------------------------------------------------------------------------
__device__ __forceinline__ void gemm64_512(const float* __restrict__ X,
                                           const float* __restrict__ W,
                                           float* sXT, float* sWT,
                                           int tid, int tx, int ty,
                                           float acc[4][4]) {
    for (int kc = 0; kc < DIMC; kc += 64) {
        __syncthreads();   // previous consumers of sXT/sWT done
        #pragma unroll
        for (int r = 0; r < 16; r++) {
            int e   = tid + r * 256;
            int row = e >> 6;        // 0..63
            int col = e & 63;        // 0..63 (contiguous in gmem -> coalesced)
            sXT[col * PAD + row] = X[row * DIMC + kc + col];
            sWT[col * PAD + row] = W[row * DIMC + kc + col];
        }
        __syncthreads();
        #pragma unroll 16
        for (int kk = 0; kk < 64; kk++) {
            const float4 a4 = *(const float4*)(sXT + kk * PAD + (ty << 2));
            const float4 b4 = *(const float4*)(sWT + kk * PAD + (tx << 2));
            float a[4] = {a4.x, a4.y, a4.z, a4.w};
            float b[4] = {b4.x, b4.y, b4.z, b4.w};
            #pragma unroll
            for (int i = 0; i < 4; i++)
                #pragma unroll
                for (int j = 0; j < 4; j++)
                    acc[i][j] = fmaf(a[i], b[j], acc[i][j]);
        }
    }
}

// ---------------------------------------------------------------------------
// Kernel 1: one block per (batch, head). Computes Qh, Kh, Vh (64x64 each) from
// the raw inputs + weights, then masked-softmax attention, writes O into
// g_x[b, token, h*64 + d].
// ---------------------------------------------------------------------------
__global__ __launch_bounds__(256, 2)
void attn_fused(const float* __restrict__ q,  const float* __restrict__ k,
                const float* __restrict__ v,  const int*   __restrict__ mask,
                const float* __restrict__ Wq, const float* __restrict__ bq,
                const float* __restrict__ Wk, const float* __restrict__ bk,
                const float* __restrict__ Wv, const float* __restrict__ bv) {
    extern __shared__ float smem[];
    float* sXT = smem;                   // 64*PAD   (working X tile, transposed)
    float* sWT = smem + 1 * 64 * PAD;    // 64*PAD   (working W tile, transposed)
    float* sQT = smem + 2 * 64 * PAD;    // Q^T : [d][token]
    float* sKT = smem + 3 * 64 * PAD;    // K^T : [d][token]
    float* sV  = smem + 4 * 64 * PAD;    // V   : [token][d]
    int*   smask = (int*)(smem + 5 * 64 * PAD);
    float* sST = sXT;                    // scores S^T : [key j][query i] (reuses X/W area)

    const int blk = blockIdx.x;
    const int h   = blk & (HEADS - 1);
    const int b   = blk >> 3;
    const int tid = threadIdx.x;
    const int tx  = tid & 15;            // 16 cols of 4
    const int ty  = tid >> 4;            // 16 rows of 4

    if (tid < NTOK) smask[tid] = mask[b * NTOK + tid];

    // ---- Q projection (scale folded in), stored transposed [d][i] ----
    {
        float acc[4][4] = {};
        gemm64_512(q + (size_t)b * NTOK * DIMC, Wq + (size_t)h * HD * DIMC,
                   sXT, sWT, tid, tx, ty, acc);
        #pragma unroll
        for (int dd = 0; dd < 4; dd++) {
            float bias = bq[h * HD + (tx << 2) + dd];
            #pragma unroll
            for (int ii = 0; ii < 4; ii++)
                sQT[((tx << 2) + dd) * PAD + (ty << 2) + ii] =
                    (acc[ii][dd] + bias) * SCALE_Q;
        }
    }
    // ---- K projection, stored transposed [d][j] ----
    {
        float acc[4][4] = {};
        gemm64_512(k + (size_t)b * NTOK * DIMC, Wk + (size_t)h * HD * DIMC,
                   sXT, sWT, tid, tx, ty, acc);
        #pragma unroll
        for (int dd = 0; dd < 4; dd++) {
            float bias = bk[h * HD + (tx << 2) + dd];
            #pragma unroll
            for (int ii = 0; ii < 4; ii++)
                sKT[((tx << 2) + dd) * PAD + (ty << 2) + ii] = acc[ii][dd] + bias;
        }
    }
    // ---- V projection, stored natural [token j][d] ----
    {
        float acc[4][4] = {};
        gemm64_512(v + (size_t)b * NTOK * DIMC, Wv + (size_t)h * HD * DIMC,
                   sXT, sWT, tid, tx, ty, acc);
        #pragma unroll
        for (int ii = 0; ii < 4; ii++) {
            #pragma unroll
            for (int dd = 0; dd < 4; dd++)
                sV[((ty << 2) + ii) * PAD + (tx << 2) + dd] =
                    acc[ii][dd] + bv[h * HD + (tx << 2) + dd];
        }
    }
    __syncthreads();   // Q/K/V tiles fully materialized; sXT free for reuse

    // ---- S^T[j][i] = sum_d K[j][d] * Qscaled[i][d], with key mask ----
    {
        float acc[4][4] = {};   // acc[jj][ii]
        #pragma unroll 16
        for (int d = 0; d < 64; d++) {
            const float4 k4 = *(const float4*)(sKT + d * PAD + (ty << 2));  // keys
            const float4 q4 = *(const float4*)(sQT + d * PAD + (tx << 2));  // queries
            float kk[4] = {k4.x, k4.y, k4.z, k4.w};
            float qq[4] = {q4.x, q4.y, q4.z, q4.w};
            #pragma unroll
            for (int jj = 0; jj < 4; jj++)
                #pragma unroll
                for (int ii = 0; ii < 4; ii++)
                    acc[jj][ii] = fmaf(kk[jj], qq[ii], acc[jj][ii]);
        }
        #pragma unroll
        for (int jj = 0; jj < 4; jj++) {
            int j = (ty << 2) + jj;
            bool keep = (smask[j] != 0);
            #pragma unroll
            for (int ii = 0; ii < 4; ii++)
                sST[j * PAD + (tx << 2) + ii] = keep ? acc[jj][ii] : -10000.0f;
        }
    }
    __syncthreads();

    // ---- softmax over keys (per query row i). 4 lanes cooperate per row. ----
    {
        int row = tid >> 2;        // query index 0..63
        int p   = tid & 3;         // 16-key slice
        float vreg[16];
        float m = -1e30f;
        #pragma unroll
        for (int s = 0; s < 16; s++) {
            vreg[s] = sST[(p * 16 + s) * PAD + row];
            m = fmaxf(m, vreg[s]);
        }
        m = fmaxf(m, __shfl_xor_sync(0xffffffffu, m, 1));
        m = fmaxf(m, __shfl_xor_sync(0xffffffffu, m, 2));
        float sum = 0.f;
        #pragma unroll
        for (int s = 0; s < 16; s++) {
            vreg[s] = __expf(vreg[s] - m);
            sum += vreg[s];
        }
        sum += __shfl_xor_sync(0xffffffffu, sum, 1);
        sum += __shfl_xor_sync(0xffffffffu, sum, 2);
        float inv = 1.0f / sum;
        #pragma unroll
        for (int s = 0; s < 16; s++)
            sST[(p * 16 + s) * PAD + row] = vreg[s] * inv;
    }
    __syncthreads();

    // ---- O[i][d] = sum_j P^T[j][i] * V[j][d]; write to g_x[b, i, h*64+d] ----
    {
        float acc[4][4] = {};   // acc[ii][dd]
        #pragma unroll 16
        for (int j = 0; j < 64; j++) {
            const float4 p4 = *(const float4*)(sST + j * PAD + (ty << 2));
            const float4 v4 = *(const float4*)(sV  + j * PAD + (tx << 2));
            float pp[4] = {p4.x, p4.y, p4.z, p4.w};
            float vv[4] = {v4.x, v4.y, v4.z, v4.w};
            #pragma unroll
            for (int ii = 0; ii < 4; ii++)
                #pragma unroll
                for (int dd = 0; dd < 4; dd++)
                    acc[ii][dd] = fmaf(pp[ii], vv[dd], acc[ii][dd]);
        }
        #pragma unroll
        for (int ii = 0; ii < 4; ii++) {
            float4 o = make_float4(acc[ii][0], acc[ii][1], acc[ii][2], acc[ii][3]);
            size_t off = ((size_t)b * NTOK + (ty << 2) + ii) * DIMC + h * HD + (tx << 2);
            *(float4*)(g_x + off) = o;
        }
    }
}

// ---------------------------------------------------------------------------
// Kernel 2: out = g_x (131072 x 512) @ Wp^T + bp. 64x64 tiles, same micro-kernel.
// ---------------------------------------------------------------------------
__global__ __launch_bounds__(256, 2)
void proj_out(const float* __restrict__ Wp, const float* __restrict__ bp,
              float* __restrict__ out) {
    __shared__ float sAT[64 * PAD];
    __shared__ float sBT[64 * PAD];

    const int m0  = blockIdx.x * 64;
    const int n0  = blockIdx.y * 64;
    const int tid = threadIdx.x;
    const int tx  = tid & 15;
    const int ty  = tid >> 4;

    float acc[4][4] = {};   // acc[mm][nn]
    for (int kc = 0; kc < DIMC; kc += 64) {
        __syncthreads();
        #pragma unroll
        for (int r = 0; r < 16; r++) {
            int e   = tid + r * 256;
            int row = e >> 6;
            int col = e & 63;
            sAT[col * PAD + row] = g_x[(size_t)(m0 + row) * DIMC + kc + col];
            sBT[col * PAD + row] = Wp[(size_t)(n0 + row) * DIMC + kc + col];
        }
        __syncthreads();
        #pragma unroll 16
        for (int kk = 0; kk < 64; kk++) {
            const float4 a4 = *(const float4*)(sAT + kk * PAD + (ty << 2));
            const float4 b4 = *(const float4*)(sBT + kk * PAD + (tx << 2));
            float a[4] = {a4.x, a4.y, a4.z, a4.w};
            float b[4] = {b4.x, b4.y, b4.z, b4.w};
            #pragma unroll
            for (int i = 0; i < 4; i++)
                #pragma unroll
                for (int j = 0; j < 4; j++)
                    acc[i][j] = fmaf(a[i], b[j], acc[i][j]);
        }
    }
    #pragma unroll
    for (int mm = 0; mm < 4; mm++) {
        float4 o;
        o.x = acc[mm][0] + bp[n0 + (tx << 2) + 0];
        o.y = acc[mm][1] + bp[n0 + (tx << 2) + 1];
        o.z = acc[mm][2] + bp[n0 + (tx << 2) + 2];
        o.w = acc[mm][3] + bp[n0 + (tx << 2) + 3];
        size_t off = (size_t)(m0 + (ty << 2) + mm) * DIMC + n0 + (tx << 2);
        *(float4*)(out + off) = o;
    }
}

extern "C" void kernel_launch(void* const* d_in, const int* in_sizes, int n_in,
                              void* d_out, int out_size) {
    const float* q    = (const float*)d_in[0];
    const float* k    = (const float*)d_in[1];
    const float* v    = (const float*)d_in[2];
    const int*   mask = (const int*)  d_in[3];
    const float* Wq   = (const float*)d_in[4];
    const float* bq   = (const float*)d_in[5];
    const float* Wk   = (const float*)d_in[6];
    const float* bk   = (const float*)d_in[7];
    const float* Wv   = (const float*)d_in[8];
    const float* bv   = (const float*)d_in[9];
    const float* Wp   = (const float*)d_in[10];
    const float* bp   = (const float*)d_in[11];
    float* out = (float*)d_out;

    const int smem1 = (5 * 64 * PAD) * (int)sizeof(float) + NTOK * (int)sizeof(int);
    cudaFuncSetAttribute(attn_fused, cudaFuncAttributeMaxDynamicSharedMemorySize, smem1);

    attn_fused<<<BATCH * HEADS, 256, smem1>>>(q, k, v, mask,
                                              Wq, bq, Wk, bk, Wv, bv);

    dim3 g2((BATCH * NTOK) / 64, DIMC / 64);
    proj_out<<<g2, 256>>>(Wp, bp, out);
}

// round 4
// speedup vs baseline: 2.0708x; 2.0708x over previous
#include <cuda_runtime.h>
#include <cuda_bf16.h>
#include <cstdint>

#define DIMC   512
#define HEADS  8
#define HD     64
#define NTOK   64
#define BATCH  2048
#define MROWS  (BATCH * NTOK)     // 131072
#define SCALE_Q 0.125f
#define PAD    68

// ---------------- device scratch (no cudaMalloc allowed) ----------------
__device__ float g_y[(size_t)3 * MROWS * DIMC];                    // Qh|Kh|Vh
__device__ float g_x[(size_t)MROWS * DIMC];                        // attn out
__device__ __align__(128) __nv_bfloat16 g_wblob[(size_t)8 * 512 * 512]; // [g*2+part][n][k]

// ---------------------------------------------------------------------------
// Kernel 0: weights -> hi/lo bf16 blobs, plain [n][k] row-major.
// ---------------------------------------------------------------------------
__global__ void conv_w(const float* __restrict__ Wq, const float* __restrict__ Wk,
                       const float* __restrict__ Wv, const float* __restrict__ Wp) {
    int idx = blockIdx.x * 256 + threadIdx.x;      // 0 .. 4*512*512-1
    int g   = idx >> 18;
    int rem = idx & 262143;                        // n*512 + k
    const float* W = (g == 0) ? Wq : (g == 1) ? Wk : (g == 2) ? Wv : Wp;
    float w = W[rem];
    __nv_bfloat16 hi = __float2bfloat16(w);
    __nv_bfloat16 lo = __float2bfloat16(w - __bfloat162float(hi));
    g_wblob[(size_t)(g * 2 + 0) * 262144 + rem] = hi;
    g_wblob[(size_t)(g * 2 + 1) * 262144 + rem] = lo;
}

// ---------------------------------------------------------------------------
// Kernel 1: C[131072,512] = A @ W^T + bias via bf16 mma.sync, hi/lo 3-product.
// CTA: 128(m) x 128(n), K chunks of 64. 8 warps: 2(m) x 4(n), warp tile 64x32.
// ---------------------------------------------------------------------------
#define SAK 72                       // smem k-stride (bf16 elems), conflict-free
#define SA_BYTES (128 * SAK * 2)     // 18432 per part

__device__ __forceinline__ void mma16816(float* d, const uint32_t* a, const uint32_t* b) {
    asm volatile(
        "mma.sync.aligned.m16n8k16.row.col.f32.bf16.bf16.f32 "
        "{%0,%1,%2,%3}, {%4,%5,%6,%7}, {%8,%9}, {%0,%1,%2,%3};"
        : "+f"(d[0]), "+f"(d[1]), "+f"(d[2]), "+f"(d[3])
        : "r"(a[0]), "r"(a[1]), "r"(a[2]), "r"(a[3]), "r"(b[0]), "r"(b[1]));
}
__device__ __forceinline__ uint32_t pack_bf(__nv_bfloat16 a, __nv_bfloat16 b) {
    return (uint32_t)__bfloat16_as_ushort(a) | ((uint32_t)__bfloat16_as_ushort(b) << 16);
}

__global__ __launch_bounds__(256, 2)
void gemm_mma(const float* __restrict__ qin, const float* __restrict__ kin,
              const float* __restrict__ vin, const float* __restrict__ bias,
              float* __restrict__ Cext, int g) {
    extern __shared__ __nv_bfloat16 sm[];
    __nv_bfloat16* sAh = sm;                     // [128 m][SAK]
    __nv_bfloat16* sAl = sm + 128 * SAK;
    __nv_bfloat16* sBh = sm + 2 * 128 * SAK;     // [128 n][SAK]
    __nv_bfloat16* sBl = sm + 3 * 128 * SAK;

    const float* A = (g == 0) ? qin : (g == 1) ? kin : (g == 2) ? vin : (const float*)g_x;
    float* C = (g < 3) ? (g_y + (size_t)g * MROWS * DIMC) : Cext;
    const __nv_bfloat16* Wh = g_wblob + (size_t)(g * 2 + 0) * 262144;
    const __nv_bfloat16* Wl = g_wblob + (size_t)(g * 2 + 1) * 262144;

    const int tid   = threadIdx.x;
    const int lane  = tid & 31;
    const int wid   = tid >> 5;
    const int wm    = (wid >> 2) * 64;     // warp m offset (0/64)
    const int wn    = (wid & 3) * 32;      // warp n offset
    const int m0    = blockIdx.x * 128;
    const int n0    = blockIdx.y * 128;

    float acc[4][4][4];
    #pragma unroll
    for (int i = 0; i < 4; i++)
        #pragma unroll
        for (int j = 0; j < 4; j++)
            #pragma unroll
            for (int r = 0; r < 4; r++) acc[i][j][r] = 0.f;

    const int arow = tid >> 1;                 // A staging: 2 threads per row
    const int acol = (tid & 1) * 32;           // 32 floats each
    const int brow = tid >> 1;                 // B staging: row n, 2 threads/row
    const int bcol = (tid & 1) * 32;

    for (int c = 0; c < 8; c++) {
        __syncthreads();
        // ---- stage A chunk (fp32 -> hi/lo bf16) ----
        {
            const float* src = A + (size_t)(m0 + arow) * DIMC + c * 64 + acol;
            #pragma unroll
            for (int u = 0; u < 8; u++) {
                float4 f = __ldg((const float4*)(src + u * 4));
                __nv_bfloat16 h0 = __float2bfloat16(f.x), h1 = __float2bfloat16(f.y),
                              h2 = __float2bfloat16(f.z), h3 = __float2bfloat16(f.w);
                __nv_bfloat16 l0 = __float2bfloat16(f.x - __bfloat162float(h0));
                __nv_bfloat16 l1 = __float2bfloat16(f.y - __bfloat162float(h1));
                __nv_bfloat16 l2 = __float2bfloat16(f.z - __bfloat162float(h2));
                __nv_bfloat16 l3 = __float2bfloat16(f.w - __bfloat162float(h3));
                int o = arow * SAK + acol + u * 4;
                *(uint2*)(sAh + o) = make_uint2(pack_bf(h0, h1), pack_bf(h2, h3));
                *(uint2*)(sAl + o) = make_uint2(pack_bf(l0, l1), pack_bf(l2, l3));
            }
        }
        // ---- stage B chunk (preconverted bf16, uint4 copies) ----
        {
            const __nv_bfloat16* sh = Wh + (size_t)(n0 + brow) * DIMC + c * 64 + bcol;
            const __nv_bfloat16* sl = Wl + (size_t)(n0 + brow) * DIMC + c * 64 + bcol;
            int o = brow * SAK + bcol;
            #pragma unroll
            for (int u = 0; u < 4; u++) {
                *(uint4*)(sBh + o + u * 8) = __ldg((const uint4*)(sh + u * 8));
                *(uint4*)(sBl + o + u * 8) = __ldg((const uint4*)(sl + u * 8));
            }
        }
        __syncthreads();

        // ---- 4 k-steps of 16 ----
        #pragma unroll
        for (int ks = 0; ks < 4; ks++) {
            const int kc = ks * 16 + (lane & 3) * 2;
            uint32_t Bh[4][2], Bl[4][2];
            #pragma unroll
            for (int j = 0; j < 4; j++) {
                int n = wn + j * 8 + (lane >> 2);
                Bh[j][0] = *(const uint32_t*)(sBh + n * SAK + kc);
                Bh[j][1] = *(const uint32_t*)(sBh + n * SAK + kc + 8);
                Bl[j][0] = *(const uint32_t*)(sBl + n * SAK + kc);
                Bl[j][1] = *(const uint32_t*)(sBl + n * SAK + kc + 8);
            }
            #pragma unroll
            for (int i = 0; i < 4; i++) {
                int r = wm + i * 16 + (lane >> 2);
                uint32_t Ah[4], Al[4];
                Ah[0] = *(const uint32_t*)(sAh + r * SAK + kc);
                Ah[1] = *(const uint32_t*)(sAh + (r + 8) * SAK + kc);
                Ah[2] = *(const uint32_t*)(sAh + r * SAK + kc + 8);
                Ah[3] = *(const uint32_t*)(sAh + (r + 8) * SAK + kc + 8);
                Al[0] = *(const uint32_t*)(sAl + r * SAK + kc);
                Al[1] = *(const uint32_t*)(sAl + (r + 8) * SAK + kc);
                Al[2] = *(const uint32_t*)(sAl + r * SAK + kc + 8);
                Al[3] = *(const uint32_t*)(sAl + (r + 8) * SAK + kc + 8);
                #pragma unroll
                for (int j = 0; j < 4; j++) {
                    mma16816(acc[i][j], Ah, Bh[j]);
                    mma16816(acc[i][j], Ah, Bl[j]);
                    mma16816(acc[i][j], Al, Bh[j]);
                }
            }
        }
    }

    // ---- epilogue: + bias, direct stores ----
    #pragma unroll
    for (int j = 0; j < 4; j++) {
        int col = n0 + wn + j * 8 + (lane & 3) * 2;
        float b0 = __ldg(bias + col), b1 = __ldg(bias + col + 1);
        #pragma unroll
        for (int i = 0; i < 4; i++) {
            int row = m0 + wm + i * 16 + (lane >> 2);
            float2 v0 = make_float2(acc[i][j][0] + b0, acc[i][j][1] + b1);
            float2 v1 = make_float2(acc[i][j][2] + b0, acc[i][j][3] + b1);
            *(float2*)(C + (size_t)row * DIMC + col) = v0;
            *(float2*)(C + (size_t)(row + 8) * DIMC + col) = v1;
        }
    }
}

// ---------------------------------------------------------------------------
// Kernel 2: attention per (b,h) — fp32 in SMEM, reads Qh/Kh/Vh from g_y.
// ---------------------------------------------------------------------------
__global__ __launch_bounds__(256, 2)
void attn(const int* __restrict__ mask) {
    extern __shared__ float smf[];
    float* sQT = smf;                  // [d][i]
    float* sKT = smf + 1 * 64 * PAD;   // [d][j]
    float* sV  = smf + 2 * 64 * PAD;   // [j][d]
    float* sS  = smf + 3 * 64 * PAD;   // [j][i]
    int* smask = (int*)(smf + 4 * 64 * PAD);

    const int blk = blockIdx.x;
    const int h   = blk & (HEADS - 1);
    const int b   = blk >> 3;
    const int tid = threadIdx.x;
    const int tx  = tid & 15;
    const int ty  = tid >> 4;

    const float* Yq = g_y;
    const float* Yk = g_y + (size_t)1 * MROWS * DIMC;
    const float* Yv = g_y + (size_t)2 * MROWS * DIMC;

    if (tid < NTOK) smask[tid] = mask[b * NTOK + tid];
    #pragma unroll
    for (int it = 0; it < 16; it++) {
        int e = tid + it * 256;
        int i = e >> 6, d = e & 63;
        size_t off = (size_t)(b * 64 + i) * 512 + h * 64 + d;
        sQT[d * PAD + i] = Yq[off] * SCALE_Q;
        sKT[d * PAD + i] = Yk[off];
        sV[i * PAD + d]  = Yv[off];
    }
    __syncthreads();

    {
        float acc[4][4] = {};
        #pragma unroll 16
        for (int d = 0; d < 64; d++) {
            const float4 k4 = *(const float4*)(sKT + d * PAD + (ty << 2));
            const float4 q4 = *(const float4*)(sQT + d * PAD + (tx << 2));
            float kk[4] = {k4.x, k4.y, k4.z, k4.w};
            float qq[4] = {q4.x, q4.y, q4.z, q4.w};
            #pragma unroll
            for (int jj = 0; jj < 4; jj++)
                #pragma unroll
                for (int ii = 0; ii < 4; ii++)
                    acc[jj][ii] = fmaf(kk[jj], qq[ii], acc[jj][ii]);
        }
        #pragma unroll
        for (int jj = 0; jj < 4; jj++) {
            int j = (ty << 2) + jj;
            bool keep = (smask[j] != 0);
            #pragma unroll
            for (int ii = 0; ii < 4; ii++)
                sS[j * PAD + (tx << 2) + ii] = keep ? acc[jj][ii] : -10000.0f;
        }
    }
    __syncthreads();

    {
        int row = tid >> 2;
        int p   = tid & 3;
        float vreg[16];
        float m = -1e30f;
        #pragma unroll
        for (int s = 0; s < 16; s++) {
            vreg[s] = sS[(p * 16 + s) * PAD + row];
            m = fmaxf(m, vreg[s]);
        }
        m = fmaxf(m, __shfl_xor_sync(0xffffffffu, m, 1));
        m = fmaxf(m, __shfl_xor_sync(0xffffffffu, m, 2));
        float sum = 0.f;
        #pragma unroll
        for (int s = 0; s < 16; s++) { vreg[s] = __expf(vreg[s] - m); sum += vreg[s]; }
        sum += __shfl_xor_sync(0xffffffffu, sum, 1);
        sum += __shfl_xor_sync(0xffffffffu, sum, 2);
        float inv = 1.0f / sum;
        #pragma unroll
        for (int s = 0; s < 16; s++) sS[(p * 16 + s) * PAD + row] = vreg[s] * inv;
    }
    __syncthreads();

    {
        float acc[4][4] = {};
        #pragma unroll 16
        for (int j = 0; j < 64; j++) {
            const float4 p4 = *(const float4*)(sS + j * PAD + (ty << 2));
            const float4 v4 = *(const float4*)(sV + j * PAD + (tx << 2));
            float pp[4] = {p4.x, p4.y, p4.z, p4.w};
            float vv[4] = {v4.x, v4.y, v4.z, v4.w};
            #pragma unroll
            for (int ii = 0; ii < 4; ii++)
                #pragma unroll
                for (int dd = 0; dd < 4; dd++)
                    acc[ii][dd] = fmaf(pp[ii], vv[dd], acc[ii][dd]);
        }
        #pragma unroll
        for (int ii = 0; ii < 4; ii++) {
            float4 o = make_float4(acc[ii][0], acc[ii][1], acc[ii][2], acc[ii][3]);
            size_t off = ((size_t)b * NTOK + (ty << 2) + ii) * DIMC + h * HD + (tx << 2);
            *(float4*)(g_x + off) = o;
        }
    }
}

// ---------------------------------------------------------------------------
extern "C" void kernel_launch(void* const* d_in, const int* in_sizes, int n_in,
                              void* d_out, int out_size) {
    const float* q    = (const float*)d_in[0];
    const float* k    = (const float*)d_in[1];
    const float* v    = (const float*)d_in[2];
    const int*   mask = (const int*)  d_in[3];
    const float* Wq   = (const float*)d_in[4];
    const float* bq   = (const float*)d_in[5];
    const float* Wk   = (const float*)d_in[6];
    const float* bk   = (const float*)d_in[7];
    const float* Wv   = (const float*)d_in[8];
    const float* bv   = (const float*)d_in[9];
    const float* Wp   = (const float*)d_in[10];
    const float* bp   = (const float*)d_in[11];
    float* out = (float*)d_out;

    const int smemG = 4 * SA_BYTES;                     // 73728
    const int smemA = 4 * 64 * PAD * (int)sizeof(float) + NTOK * (int)sizeof(int);
    cudaFuncSetAttribute(gemm_mma, cudaFuncAttributeMaxDynamicSharedMemorySize, smemG);
    cudaFuncSetAttribute(attn, cudaFuncAttributeMaxDynamicSharedMemorySize, smemA);

    conv_w<<<4096, 256>>>(Wq, Wk, Wv, Wp);

    dim3 gg(MROWS / 128, DIMC / 128);
    gemm_mma<<<gg, 256, smemG>>>(q, k, v, bq, nullptr, 0);
    gemm_mma<<<gg, 256, smemG>>>(q, k, v, bk, nullptr, 1);
    gemm_mma<<<gg, 256, smemG>>>(q, k, v, bv, nullptr, 2);

    attn<<<BATCH * HEADS, 256, smemA>>>(mask);

    gemm_mma<<<gg, 256, smemG>>>(q, k, v, bp, out, 3);
}

// round 5
// speedup vs baseline: 2.6215x; 1.2659x over previous
#include <cuda_runtime.h>
#include <cuda_bf16.h>
#include <cstdint>

#define DIMC   512
#define HEADS  8
#define HD     64
#define NTOK   64
#define BATCH  2048
#define MROWS  (BATCH * NTOK)     // 131072
#define SCALE_Q 0.125f
#define PAD    68

// ---------------- device scratch (no cudaMalloc allowed) ----------------
__device__ float g_y[(size_t)3 * MROWS * DIMC];                    // Qh|Kh|Vh
__device__ float g_x[(size_t)MROWS * DIMC];                        // attn out
__device__ __align__(128) __nv_bfloat16 g_wblob[(size_t)8 * 512 * 512]; // [g*2+part][n][k]

// ---------------------------------------------------------------------------
// Kernel 0: weights -> hi/lo bf16 blobs, [n][k] row-major.
// ---------------------------------------------------------------------------
__global__ void conv_w(const float* __restrict__ Wq, const float* __restrict__ Wk,
                       const float* __restrict__ Wv, const float* __restrict__ Wp) {
    int idx = blockIdx.x * 256 + threadIdx.x;
    int g   = idx >> 18;
    int rem = idx & 262143;
    const float* W = (g == 0) ? Wq : (g == 1) ? Wk : (g == 2) ? Wv : Wp;
    float w = W[rem];
    __nv_bfloat16 hi = __float2bfloat16(w);
    __nv_bfloat16 lo = __float2bfloat16(w - __bfloat162float(hi));
    g_wblob[(size_t)(g * 2 + 0) * 262144 + rem] = hi;
    g_wblob[(size_t)(g * 2 + 1) * 262144 + rem] = lo;
}

// ---------------------------------------------------------------------------
// GEMM: C[131072,512] = A @ W^T + bias. bf16 hi/lo 3-product mma.sync.
// CTA 128m x 256n, K chunks of 32, 3-stage cp.async pipeline, ldmatrix frags.
// 8 warps = 2(m) x 4(n), warp tile 64x64.
// ---------------------------------------------------------------------------
#define KC      32
#define SAK     40                          // padded k-stride (bf16), LDSM conflict-free
#define OFF_AH  0
#define OFF_AL  (128 * SAK)
#define OFF_BH  (2 * 128 * SAK)
#define OFF_BL  (2 * 128 * SAK + 256 * SAK)
#define STAGE_E (2 * 128 * SAK + 2 * 256 * SAK)   // 30720 bf16 elems
#define SMEM_G  (3 * STAGE_E * 2)                  // 184320 bytes

__device__ __forceinline__ void mma16816(float* d, const uint32_t* a, const uint32_t* b) {
    asm volatile(
        "mma.sync.aligned.m16n8k16.row.col.f32.bf16.bf16.f32 "
        "{%0,%1,%2,%3}, {%4,%5,%6,%7}, {%8,%9}, {%0,%1,%2,%3};"
        : "+f"(d[0]), "+f"(d[1]), "+f"(d[2]), "+f"(d[3])
        : "r"(a[0]), "r"(a[1]), "r"(a[2]), "r"(a[3]), "r"(b[0]), "r"(b[1]));
}
__device__ __forceinline__ void ldsm_x4(uint32_t* r, uint32_t addr) {
    asm volatile("ldmatrix.sync.aligned.m8n8.x4.shared.b16 {%0,%1,%2,%3}, [%4];"
        : "=r"(r[0]), "=r"(r[1]), "=r"(r[2]), "=r"(r[3]) : "r"(addr));
}
__device__ __forceinline__ void cp16(uint32_t dst, const void* src) {
    asm volatile("cp.async.cg.shared.global [%0], [%1], 16;" :: "r"(dst), "l"(src));
}
__device__ __forceinline__ uint32_t pack_bf(__nv_bfloat16 a, __nv_bfloat16 b) {
    return (uint32_t)__bfloat16_as_ushort(a) | ((uint32_t)__bfloat16_as_ushort(b) << 16);
}

__global__ __launch_bounds__(256, 1)
void gemm_mma(const float* __restrict__ qin, const float* __restrict__ kin,
              const float* __restrict__ vin, const float* __restrict__ bias,
              float* __restrict__ Cext, int g) {
    extern __shared__ __nv_bfloat16 sm[];
    const uint32_t sb = (uint32_t)__cvta_generic_to_shared(sm);

    const float* A = (g == 0) ? qin : (g == 1) ? kin : (g == 2) ? vin : (const float*)g_x;
    float* C = (g < 3) ? (g_y + (size_t)g * MROWS * DIMC) : Cext;
    const __nv_bfloat16* Wh = g_wblob + (size_t)(g * 2 + 0) * 262144;
    const __nv_bfloat16* Wl = g_wblob + (size_t)(g * 2 + 1) * 262144;

    const int tid  = threadIdx.x;
    const int lane = tid & 31;
    const int wid  = tid >> 5;
    const int wm   = (wid >> 2) * 64;
    const int wn   = (wid & 3) * 64;
    const int n0   = blockIdx.x * 256;   // x fastest -> 2 n-tiles of same m adjacent (L2 A reuse)
    const int m0   = blockIdx.y * 128;

    // staging indices
    const int arow  = tid >> 1;
    const int acolf = (tid & 1) * 16;

    // ldmatrix lane offsets (bf16 elements)
    const int a_lrow = (lane & 15);
    const int a_lcol = (lane >> 4) * 8;
    const int b_lrow = ((lane >> 4) << 3) + (lane & 7);
    const int b_lcol = ((lane >> 3) & 1) * 8;

    float acc[4][8][4];
    #pragma unroll
    for (int i = 0; i < 4; i++)
        #pragma unroll
        for (int j = 0; j < 8; j++)
            #pragma unroll
            for (int r = 0; r < 4; r++) acc[i][j][r] = 0.f;

    float4 rA[4];

    // ---- staging helpers ----
    auto stageB = [&](int c, int st) {
        uint32_t dsth = sb + (uint32_t)(st * STAGE_E + OFF_BH + tid * SAK) * 2;
        uint32_t dstl = sb + (uint32_t)(st * STAGE_E + OFF_BL + tid * SAK) * 2;
        const __nv_bfloat16* sh = Wh + (size_t)(n0 + tid) * DIMC + c * KC;
        const __nv_bfloat16* sl = Wl + (size_t)(n0 + tid) * DIMC + c * KC;
        #pragma unroll
        for (int u = 0; u < 4; u++) {
            cp16(dsth + u * 16, sh + u * 8);
            cp16(dstl + u * 16, sl + u * 8);
        }
    };
    auto ldgA = [&](int c) {
        const float* src = A + (size_t)(m0 + arow) * DIMC + c * KC + acolf;
        #pragma unroll
        for (int u = 0; u < 4; u++) rA[u] = __ldg((const float4*)(src + u * 4));
    };
    auto stsA = [&](int st) {
        __nv_bfloat16* sAh = sm + st * STAGE_E + OFF_AH + arow * SAK + acolf;
        __nv_bfloat16* sAl = sm + st * STAGE_E + OFF_AL + arow * SAK + acolf;
        #pragma unroll
        for (int u = 0; u < 4; u++) {
            float4 f = rA[u];
            __nv_bfloat16 h0 = __float2bfloat16(f.x), h1 = __float2bfloat16(f.y),
                          h2 = __float2bfloat16(f.z), h3 = __float2bfloat16(f.w);
            __nv_bfloat16 l0 = __float2bfloat16(f.x - __bfloat162float(h0));
            __nv_bfloat16 l1 = __float2bfloat16(f.y - __bfloat162float(h1));
            __nv_bfloat16 l2 = __float2bfloat16(f.z - __bfloat162float(h2));
            __nv_bfloat16 l3 = __float2bfloat16(f.w - __bfloat162float(h3));
            *(uint2*)(sAh + u * 4) = make_uint2(pack_bf(h0, h1), pack_bf(h2, h3));
            *(uint2*)(sAl + u * 4) = make_uint2(pack_bf(l0, l1), pack_bf(l2, l3));
        }
    };
    auto compute = [&](int st) {
        const uint32_t abase = sb + (uint32_t)(st * STAGE_E) * 2;
        #pragma unroll
        for (int ks = 0; ks < 2; ks++) {
            const int kc0 = ks * 16;
            uint32_t bf[8][2];
            uint32_t ah[4][4];
            // B-hi fragments
            #pragma unroll
            for (int gg = 0; gg < 4; gg++) {
                uint32_t r[4];
                uint32_t addr = abase + (uint32_t)(OFF_BH +
                    (wn + gg * 16 + b_lrow) * SAK + kc0 + b_lcol) * 2;
                ldsm_x4(r, addr);
                bf[2 * gg][0] = r[0]; bf[2 * gg][1] = r[1];
                bf[2 * gg + 1][0] = r[2]; bf[2 * gg + 1][1] = r[3];
            }
            // products hi*hi and lo*hi
            #pragma unroll
            for (int i = 0; i < 4; i++) {
                uint32_t aaddr = abase + (uint32_t)(OFF_AH +
                    (wm + i * 16 + a_lrow) * SAK + kc0 + a_lcol) * 2;
                ldsm_x4(ah[i], aaddr);
                uint32_t al[4];
                ldsm_x4(al, aaddr + (uint32_t)(OFF_AL - OFF_AH) * 2);
                #pragma unroll
                for (int j = 0; j < 8; j++) {
                    mma16816(acc[i][j], ah[i], bf[j]);
                    mma16816(acc[i][j], al,    bf[j]);
                }
            }
            // B-lo fragments (reuse regs)
            #pragma unroll
            for (int gg = 0; gg < 4; gg++) {
                uint32_t r[4];
                uint32_t addr = abase + (uint32_t)(OFF_BL +
                    (wn + gg * 16 + b_lrow) * SAK + kc0 + b_lcol) * 2;
                ldsm_x4(r, addr);
                bf[2 * gg][0] = r[0]; bf[2 * gg][1] = r[1];
                bf[2 * gg + 1][0] = r[2]; bf[2 * gg + 1][1] = r[3];
            }
            // product hi*lo
            #pragma unroll
            for (int i = 0; i < 4; i++)
                #pragma unroll
                for (int j = 0; j < 8; j++)
                    mma16816(acc[i][j], ah[i], bf[j]);
        }
    };

    // ---- prologue: stage chunk 0 ----
    stageB(0, 0);
    asm volatile("cp.async.commit_group;" ::: "memory");
    ldgA(0);
    stsA(0);

    // ---- main pipeline: 16 chunks, 3 stages, 1 barrier per chunk ----
    for (int c = 0; c < 16; c++) {
        const int st  = c % 3;
        const int stn = (c + 1) % 3;
        if (c < 15) {
            ldgA(c + 1);                   // latency hidden under compute(c)
            stageB(c + 1, stn);
            asm volatile("cp.async.commit_group;" ::: "memory");
            asm volatile("cp.async.wait_group 1;" ::: "memory");
        } else {
            asm volatile("cp.async.wait_group 0;" ::: "memory");
        }
        __syncthreads();
        compute(st);
        if (c < 15) stsA(stn);
    }

    // ---- epilogue: + bias ----
    #pragma unroll
    for (int j = 0; j < 8; j++) {
        int col = n0 + wn + j * 8 + (lane & 3) * 2;
        float b0 = __ldg(bias + col), b1 = __ldg(bias + col + 1);
        #pragma unroll
        for (int i = 0; i < 4; i++) {
            int row = m0 + wm + i * 16 + (lane >> 2);
            *(float2*)(C + (size_t)row * DIMC + col) =
                make_float2(acc[i][j][0] + b0, acc[i][j][1] + b1);
            *(float2*)(C + (size_t)(row + 8) * DIMC + col) =
                make_float2(acc[i][j][2] + b0, acc[i][j][3] + b1);
        }
    }
}

// ---------------------------------------------------------------------------
// Attention per (b,h) — fp32 in SMEM, reads Qh/Kh/Vh from g_y, writes g_x.
// ---------------------------------------------------------------------------
__global__ __launch_bounds__(256, 2)
void attn(const int* __restrict__ mask) {
    extern __shared__ float smf[];
    float* sQT = smf;
    float* sKT = smf + 1 * 64 * PAD;
    float* sV  = smf + 2 * 64 * PAD;
    float* sS  = smf + 3 * 64 * PAD;
    int* smask = (int*)(smf + 4 * 64 * PAD);

    const int blk = blockIdx.x;
    const int h   = blk & (HEADS - 1);
    const int b   = blk >> 3;
    const int tid = threadIdx.x;
    const int tx  = tid & 15;
    const int ty  = tid >> 4;

    const float* Yq = g_y;
    const float* Yk = g_y + (size_t)1 * MROWS * DIMC;
    const float* Yv = g_y + (size_t)2 * MROWS * DIMC;

    if (tid < NTOK) smask[tid] = mask[b * NTOK + tid];
    #pragma unroll
    for (int it = 0; it < 16; it++) {
        int e = tid + it * 256;
        int i = e >> 6, d = e & 63;
        size_t off = (size_t)(b * 64 + i) * 512 + h * 64 + d;
        sQT[d * PAD + i] = Yq[off] * SCALE_Q;
        sKT[d * PAD + i] = Yk[off];
        sV[i * PAD + d]  = Yv[off];
    }
    __syncthreads();

    {
        float acc[4][4] = {};
        #pragma unroll 16
        for (int d = 0; d < 64; d++) {
            const float4 k4 = *(const float4*)(sKT + d * PAD + (ty << 2));
            const float4 q4 = *(const float4*)(sQT + d * PAD + (tx << 2));
            float kk[4] = {k4.x, k4.y, k4.z, k4.w};
            float qq[4] = {q4.x, q4.y, q4.z, q4.w};
            #pragma unroll
            for (int jj = 0; jj < 4; jj++)
                #pragma unroll
                for (int ii = 0; ii < 4; ii++)
                    acc[jj][ii] = fmaf(kk[jj], qq[ii], acc[jj][ii]);
        }
        #pragma unroll
        for (int jj = 0; jj < 4; jj++) {
            int j = (ty << 2) + jj;
            bool keep = (smask[j] != 0);
            #pragma unroll
            for (int ii = 0; ii < 4; ii++)
                sS[j * PAD + (tx << 2) + ii] = keep ? acc[jj][ii] : -10000.0f;
        }
    }
    __syncthreads();

    {
        int row = tid >> 2;
        int p   = tid & 3;
        float vreg[16];
        float m = -1e30f;
        #pragma unroll
        for (int s = 0; s < 16; s++) {
            vreg[s] = sS[(p * 16 + s) * PAD + row];
            m = fmaxf(m, vreg[s]);
        }
        m = fmaxf(m, __shfl_xor_sync(0xffffffffu, m, 1));
        m = fmaxf(m, __shfl_xor_sync(0xffffffffu, m, 2));
        float sum = 0.f;
        #pragma unroll
        for (int s = 0; s < 16; s++) { vreg[s] = __expf(vreg[s] - m); sum += vreg[s]; }
        sum += __shfl_xor_sync(0xffffffffu, sum, 1);
        sum += __shfl_xor_sync(0xffffffffu, sum, 2);
        float inv = 1.0f / sum;
        #pragma unroll
        for (int s = 0; s < 16; s++) sS[(p * 16 + s) * PAD + row] = vreg[s] * inv;
    }
    __syncthreads();

    {
        float acc[4][4] = {};
        #pragma unroll 16
        for (int j = 0; j < 64; j++) {
            const float4 p4 = *(const float4*)(sS + j * PAD + (ty << 2));
            const float4 v4 = *(const float4*)(sV + j * PAD + (tx << 2));
            float pp[4] = {p4.x, p4.y, p4.z, p4.w};
            float vv[4] = {v4.x, v4.y, v4.z, v4.w};
            #pragma unroll
            for (int ii = 0; ii < 4; ii++)
                #pragma unroll
                for (int dd = 0; dd < 4; dd++)
                    acc[ii][dd] = fmaf(pp[ii], vv[dd], acc[ii][dd]);
        }
        #pragma unroll
        for (int ii = 0; ii < 4; ii++) {
            float4 o = make_float4(acc[ii][0], acc[ii][1], acc[ii][2], acc[ii][3]);
            size_t off = ((size_t)b * NTOK + (ty << 2) + ii) * DIMC + h * HD + (tx << 2);
            *(float4*)(g_x + off) = o;
        }
    }
}

// ---------------------------------------------------------------------------
extern "C" void kernel_launch(void* const* d_in, const int* in_sizes, int n_in,
                              void* d_out, int out_size) {
    const float* q    = (const float*)d_in[0];
    const float* k    = (const float*)d_in[1];
    const float* v    = (const float*)d_in[2];
    const int*   mask = (const int*)  d_in[3];
    const float* Wq   = (const float*)d_in[4];
    const float* bq   = (const float*)d_in[5];
    const float* Wk   = (const float*)d_in[6];
    const float* bk   = (const float*)d_in[7];
    const float* Wv   = (const float*)d_in[8];
    const float* bv   = (const float*)d_in[9];
    const float* Wp   = (const float*)d_in[10];
    const float* bp   = (const float*)d_in[11];
    float* out = (float*)d_out;

    const int smemA = 4 * 64 * PAD * (int)sizeof(float) + NTOK * (int)sizeof(int);
    cudaFuncSetAttribute(gemm_mma, cudaFuncAttributeMaxDynamicSharedMemorySize, SMEM_G);
    cudaFuncSetAttribute(attn, cudaFuncAttributeMaxDynamicSharedMemorySize, smemA);

    conv_w<<<4096, 256>>>(Wq, Wk, Wv, Wp);

    dim3 gg(DIMC / 256, MROWS / 128);
    gemm_mma<<<gg, 256, SMEM_G>>>(q, k, v, bq, nullptr, 0);
    gemm_mma<<<gg, 256, SMEM_G>>>(q, k, v, bk, nullptr, 1);
    gemm_mma<<<gg, 256, SMEM_G>>>(q, k, v, bv, nullptr, 2);

    attn<<<BATCH * HEADS, 256, smemA>>>(mask);

    gemm_mma<<<gg, 256, SMEM_G>>>(q, k, v, bp, out, 3);
}

// round 6
// speedup vs baseline: 2.9727x; 1.1340x over previous
#include <cuda_runtime.h>
#include <cuda_bf16.h>
#include <cstdint>

#define DIMC   512
#define HEADS  8
#define HD     64
#define NTOK   64
#define BATCH  2048
#define MROWS  (BATCH * NTOK)     // 131072
#define SCALE_Q 0.125f
#define PAD    68

// ---------------- device scratch ----------------
__device__ float g_y[(size_t)3 * MROWS * DIMC];                    // Qh|Kh|Vh
__device__ float g_x[(size_t)MROWS * DIMC];                        // attn out
__device__ __align__(128) __nv_bfloat16 g_wblob[(size_t)8 * 512 * 512]; // [g*2+part][n][k]

// ---------------------------------------------------------------------------
// Kernel 0: weights -> hi/lo bf16 blobs, [n][k] row-major.
// ---------------------------------------------------------------------------
__global__ void conv_w(const float* __restrict__ Wq, const float* __restrict__ Wk,
                       const float* __restrict__ Wv, const float* __restrict__ Wp) {
    int idx = blockIdx.x * 256 + threadIdx.x;
    int g   = idx >> 18;
    int rem = idx & 262143;
    const float* W = (g == 0) ? Wq : (g == 1) ? Wk : (g == 2) ? Wv : Wp;
    float w = W[rem];
    __nv_bfloat16 hi = __float2bfloat16(w);
    __nv_bfloat16 lo = __float2bfloat16(w - __bfloat162float(hi));
    g_wblob[(size_t)(g * 2 + 0) * 262144 + rem] = hi;
    g_wblob[(size_t)(g * 2 + 1) * 262144 + rem] = lo;
}

// ---------------------------------------------------------------------------
// GEMM: C[131072,512] = A @ W^T + bias. bf16 hi/lo 3-product mma.sync.
// CTA 128m x 256n, 512 threads = 16 warps (4m x 4n), warp tile 32x64.
// K chunks of 32, 3-stage cp.async pipeline, ldmatrix fragments.
// ---------------------------------------------------------------------------
#define KC      32
#define SAK     40
#define OFF_AH  0
#define OFF_AL  (128 * SAK)
#define OFF_BH  (2 * 128 * SAK)
#define OFF_BL  (2 * 128 * SAK + 256 * SAK)
#define STAGE_E (2 * 128 * SAK + 2 * 256 * SAK)   // 30720 bf16 elems
#define SMEM_G  (3 * STAGE_E * 2)                  // 184320 bytes

__device__ __forceinline__ void mma16816(float* d, const uint32_t* a, const uint32_t* b) {
    asm volatile(
        "mma.sync.aligned.m16n8k16.row.col.f32.bf16.bf16.f32 "
        "{%0,%1,%2,%3}, {%4,%5,%6,%7}, {%8,%9}, {%0,%1,%2,%3};"
        : "+f"(d[0]), "+f"(d[1]), "+f"(d[2]), "+f"(d[3])
        : "r"(a[0]), "r"(a[1]), "r"(a[2]), "r"(a[3]), "r"(b[0]), "r"(b[1]));
}
__device__ __forceinline__ void ldsm_x4(uint32_t* r, uint32_t addr) {
    asm volatile("ldmatrix.sync.aligned.m8n8.x4.shared.b16 {%0,%1,%2,%3}, [%4];"
        : "=r"(r[0]), "=r"(r[1]), "=r"(r[2]), "=r"(r[3]) : "r"(addr));
}
__device__ __forceinline__ void cp16(uint32_t dst, const void* src) {
    asm volatile("cp.async.cg.shared.global [%0], [%1], 16;" :: "r"(dst), "l"(src));
}
__device__ __forceinline__ uint32_t pack_bf(__nv_bfloat16 a, __nv_bfloat16 b) {
    return (uint32_t)__bfloat16_as_ushort(a) | ((uint32_t)__bfloat16_as_ushort(b) << 16);
}

__global__ __launch_bounds__(512, 1)
void gemm_mma(const float* __restrict__ qin, const float* __restrict__ kin,
              const float* __restrict__ vin, const float* __restrict__ bias,
              float* __restrict__ Cext, int g) {
    extern __shared__ __nv_bfloat16 sm[];
    const uint32_t sb = (uint32_t)__cvta_generic_to_shared(sm);

    const float* A = (g == 0) ? qin : (g == 1) ? kin : (g == 2) ? vin : (const float*)g_x;
    float* C = (g < 3) ? (g_y + (size_t)g * MROWS * DIMC) : Cext;
    const __nv_bfloat16* Wh = g_wblob + (size_t)(g * 2 + 0) * 262144;
    const __nv_bfloat16* Wl = g_wblob + (size_t)(g * 2 + 1) * 262144;

    const int tid  = threadIdx.x;
    const int lane = tid & 31;
    const int wid  = tid >> 5;
    const int wm   = (wid >> 2) * 32;     // 4 m-groups of 32
    const int wn   = (wid & 3) * 64;      // 4 n-groups of 64
    const int n0   = blockIdx.x * 256;
    const int m0   = blockIdx.y * 128;

    // A staging: 4 threads per row, 8 floats each
    const int arow  = tid >> 2;
    const int acolf = (tid & 3) * 8;
    // B staging: 512 threads = 2 parts x 256 rows, 32 bf16 per row
    const int bpart = tid >> 8;
    const int brow  = tid & 255;

    // ldmatrix lane offsets
    const int a_lrow = (lane & 15);
    const int a_lcol = (lane >> 4) * 8;
    const int b_lrow = ((lane >> 4) << 3) + (lane & 7);
    const int b_lcol = ((lane >> 3) & 1) * 8;

    float acc[2][8][4];
    #pragma unroll
    for (int i = 0; i < 2; i++)
        #pragma unroll
        for (int j = 0; j < 8; j++)
            #pragma unroll
            for (int r = 0; r < 4; r++) acc[i][j][r] = 0.f;

    float4 rA[2];

    auto stageB = [&](int c, int st) {
        uint32_t dst = sb + (uint32_t)(st * STAGE_E +
                       (bpart ? OFF_BL : OFF_BH) + brow * SAK) * 2;
        const __nv_bfloat16* src = (bpart ? Wl : Wh) + (size_t)(n0 + brow) * DIMC + c * KC;
        #pragma unroll
        for (int u = 0; u < 4; u++) cp16(dst + u * 16, src + u * 8);
    };
    auto ldgA = [&](int c) {
        const float* src = A + (size_t)(m0 + arow) * DIMC + c * KC + acolf;
        rA[0] = __ldg((const float4*)src);
        rA[1] = __ldg((const float4*)(src + 4));
    };
    auto stsA = [&](int st) {
        __nv_bfloat16* sAh = sm + st * STAGE_E + OFF_AH + arow * SAK + acolf;
        __nv_bfloat16* sAl = sm + st * STAGE_E + OFF_AL + arow * SAK + acolf;
        #pragma unroll
        for (int u = 0; u < 2; u++) {
            float4 f = rA[u];
            __nv_bfloat16 h0 = __float2bfloat16(f.x), h1 = __float2bfloat16(f.y),
                          h2 = __float2bfloat16(f.z), h3 = __float2bfloat16(f.w);
            __nv_bfloat16 l0 = __float2bfloat16(f.x - __bfloat162float(h0));
            __nv_bfloat16 l1 = __float2bfloat16(f.y - __bfloat162float(h1));
            __nv_bfloat16 l2 = __float2bfloat16(f.z - __bfloat162float(h2));
            __nv_bfloat16 l3 = __float2bfloat16(f.w - __bfloat162float(h3));
            *(uint2*)(sAh + u * 4) = make_uint2(pack_bf(h0, h1), pack_bf(h2, h3));
            *(uint2*)(sAl + u * 4) = make_uint2(pack_bf(l0, l1), pack_bf(l2, l3));
        }
    };
    auto compute = [&](int st) {
        const uint32_t abase = sb + (uint32_t)(st * STAGE_E) * 2;
        #pragma unroll
        for (int ks = 0; ks < 2; ks++) {
            const int kc0 = ks * 16;
            uint32_t bf[8][2];
            uint32_t ah[2][4];
            // B-hi fragments
            #pragma unroll
            for (int gg = 0; gg < 4; gg++) {
                uint32_t r[4];
                uint32_t addr = abase + (uint32_t)(OFF_BH +
                    (wn + gg * 16 + b_lrow) * SAK + kc0 + b_lcol) * 2;
                ldsm_x4(r, addr);
                bf[2 * gg][0] = r[0]; bf[2 * gg][1] = r[1];
                bf[2 * gg + 1][0] = r[2]; bf[2 * gg + 1][1] = r[3];
            }
            // products hi*hi and lo*hi
            #pragma unroll
            for (int i = 0; i < 2; i++) {
                uint32_t aaddr = abase + (uint32_t)(OFF_AH +
                    (wm + i * 16 + a_lrow) * SAK + kc0 + a_lcol) * 2;
                ldsm_x4(ah[i], aaddr);
                uint32_t al[4];
                ldsm_x4(al, aaddr + (uint32_t)(OFF_AL - OFF_AH) * 2);
                #pragma unroll
                for (int j = 0; j < 8; j++) {
                    mma16816(acc[i][j], ah[i], bf[j]);
                    mma16816(acc[i][j], al,    bf[j]);
                }
            }
            // B-lo fragments
            #pragma unroll
            for (int gg = 0; gg < 4; gg++) {
                uint32_t r[4];
                uint32_t addr = abase + (uint32_t)(OFF_BL +
                    (wn + gg * 16 + b_lrow) * SAK + kc0 + b_lcol) * 2;
                ldsm_x4(r, addr);
                bf[2 * gg][0] = r[0]; bf[2 * gg][1] = r[1];
                bf[2 * gg + 1][0] = r[2]; bf[2 * gg + 1][1] = r[3];
            }
            // product hi*lo
            #pragma unroll
            for (int i = 0; i < 2; i++)
                #pragma unroll
                for (int j = 0; j < 8; j++)
                    mma16816(acc[i][j], ah[i], bf[j]);
        }
    };

    // ---- prologue ----
    stageB(0, 0);
    asm volatile("cp.async.commit_group;" ::: "memory");
    ldgA(0);
    stsA(0);

    // ---- main pipeline ----
    for (int c = 0; c < 16; c++) {
        const int st  = c % 3;
        const int stn = (c + 1) % 3;
        if (c < 15) {
            ldgA(c + 1);
            stageB(c + 1, stn);
            asm volatile("cp.async.commit_group;" ::: "memory");
            asm volatile("cp.async.wait_group 1;" ::: "memory");
        } else {
            asm volatile("cp.async.wait_group 0;" ::: "memory");
        }
        __syncthreads();
        compute(st);
        if (c < 15) stsA(stn);
    }

    // ---- epilogue ----
    #pragma unroll
    for (int j = 0; j < 8; j++) {
        int col = n0 + wn + j * 8 + (lane & 3) * 2;
        float b0 = __ldg(bias + col), b1 = __ldg(bias + col + 1);
        #pragma unroll
        for (int i = 0; i < 2; i++) {
            int row = m0 + wm + i * 16 + (lane >> 2);
            *(float2*)(C + (size_t)row * DIMC + col) =
                make_float2(acc[i][j][0] + b0, acc[i][j][1] + b1);
            *(float2*)(C + (size_t)(row + 8) * DIMC + col) =
                make_float2(acc[i][j][2] + b0, acc[i][j][3] + b1);
        }
    }
}

// ---------------------------------------------------------------------------
// Attention per (b,h) — fp32 in SMEM, reads Qh/Kh/Vh from g_y, writes g_x.
// ---------------------------------------------------------------------------
__global__ __launch_bounds__(256, 2)
void attn(const int* __restrict__ mask) {
    extern __shared__ float smf[];
    float* sQT = smf;
    float* sKT = smf + 1 * 64 * PAD;
    float* sV  = smf + 2 * 64 * PAD;
    float* sS  = smf + 3 * 64 * PAD;
    int* smask = (int*)(smf + 4 * 64 * PAD);

    const int blk = blockIdx.x;
    const int h   = blk & (HEADS - 1);
    const int b   = blk >> 3;
    const int tid = threadIdx.x;
    const int tx  = tid & 15;
    const int ty  = tid >> 4;

    const float* Yq = g_y;
    const float* Yk = g_y + (size_t)1 * MROWS * DIMC;
    const float* Yv = g_y + (size_t)2 * MROWS * DIMC;

    if (tid < NTOK) smask[tid] = mask[b * NTOK + tid];
    #pragma unroll
    for (int it = 0; it < 16; it++) {
        int e = tid + it * 256;
        int i = e >> 6, d = e & 63;
        size_t off = (size_t)(b * 64 + i) * 512 + h * 64 + d;
        sQT[d * PAD + i] = Yq[off] * SCALE_Q;
        sKT[d * PAD + i] = Yk[off];
        sV[i * PAD + d]  = Yv[off];
    }
    __syncthreads();

    {
        float acc[4][4] = {};
        #pragma unroll 16
        for (int d = 0; d < 64; d++) {
            const float4 k4 = *(const float4*)(sKT + d * PAD + (ty << 2));
            const float4 q4 = *(const float4*)(sQT + d * PAD + (tx << 2));
            float kk[4] = {k4.x, k4.y, k4.z, k4.w};
            float qq[4] = {q4.x, q4.y, q4.z, q4.w};
            #pragma unroll
            for (int jj = 0; jj < 4; jj++)
                #pragma unroll
                for (int ii = 0; ii < 4; ii++)
                    acc[jj][ii] = fmaf(kk[jj], qq[ii], acc[jj][ii]);
        }
        #pragma unroll
        for (int jj = 0; jj < 4; jj++) {
            int j = (ty << 2) + jj;
            bool keep = (smask[j] != 0);
            #pragma unroll
            for (int ii = 0; ii < 4; ii++)
                sS[j * PAD + (tx << 2) + ii] = keep ? acc[jj][ii] : -10000.0f;
        }
    }
    __syncthreads();

    {
        int row = tid >> 2;
        int p   = tid & 3;
        float vreg[16];
        float m = -1e30f;
        #pragma unroll
        for (int s = 0; s < 16; s++) {
            vreg[s] = sS[(p * 16 + s) * PAD + row];
            m = fmaxf(m, vreg[s]);
        }
        m = fmaxf(m, __shfl_xor_sync(0xffffffffu, m, 1));
        m = fmaxf(m, __shfl_xor_sync(0xffffffffu, m, 2));
        float sum = 0.f;
        #pragma unroll
        for (int s = 0; s < 16; s++) { vreg[s] = __expf(vreg[s] - m); sum += vreg[s]; }
        sum += __shfl_xor_sync(0xffffffffu, sum, 1);
        sum += __shfl_xor_sync(0xffffffffu, sum, 2);
        float inv = 1.0f / sum;
        #pragma unroll
        for (int s = 0; s < 16; s++) sS[(p * 16 + s) * PAD + row] = vreg[s] * inv;
    }
    __syncthreads();

    {
        float acc[4][4] = {};
        #pragma unroll 16
        for (int j = 0; j < 64; j++) {
            const float4 p4 = *(const float4*)(sS + j * PAD + (ty << 2));
            const float4 v4 = *(const float4*)(sV + j * PAD + (tx << 2));
            float pp[4] = {p4.x, p4.y, p4.z, p4.w};
            float vv[4] = {v4.x, v4.y, v4.z, v4.w};
            #pragma unroll
            for (int ii = 0; ii < 4; ii++)
                #pragma unroll
                for (int dd = 0; dd < 4; dd++)
                    acc[ii][dd] = fmaf(pp[ii], vv[dd], acc[ii][dd]);
        }
        #pragma unroll
        for (int ii = 0; ii < 4; ii++) {
            float4 o = make_float4(acc[ii][0], acc[ii][1], acc[ii][2], acc[ii][3]);
            size_t off = ((size_t)b * NTOK + (ty << 2) + ii) * DIMC + h * HD + (tx << 2);
            *(float4*)(g_x + off) = o;
        }
    }
}

// ---------------------------------------------------------------------------
extern "C" void kernel_launch(void* const* d_in, const int* in_sizes, int n_in,
                              void* d_out, int out_size) {
    const float* q    = (const float*)d_in[0];
    const float* k    = (const float*)d_in[1];
    const float* v    = (const float*)d_in[2];
    const int*   mask = (const int*)  d_in[3];
    const float* Wq   = (const float*)d_in[4];
    const float* bq   = (const float*)d_in[5];
    const float* Wk   = (const float*)d_in[6];
    const float* bk   = (const float*)d_in[7];
    const float* Wv   = (const float*)d_in[8];
    const float* bv   = (const float*)d_in[9];
    const float* Wp   = (const float*)d_in[10];
    const float* bp   = (const float*)d_in[11];
    float* out = (float*)d_out;

    const int smemA = 4 * 64 * PAD * (int)sizeof(float) + NTOK * (int)sizeof(int);
    cudaFuncSetAttribute(gemm_mma, cudaFuncAttributeMaxDynamicSharedMemorySize, SMEM_G);
    cudaFuncSetAttribute(attn, cudaFuncAttributeMaxDynamicSharedMemorySize, smemA);

    conv_w<<<4096, 256>>>(Wq, Wk, Wv, Wp);

    dim3 gg(DIMC / 256, MROWS / 128);
    gemm_mma<<<gg, 512, SMEM_G>>>(q, k, v, bq, nullptr, 0);
    gemm_mma<<<gg, 512, SMEM_G>>>(q, k, v, bk, nullptr, 1);
    gemm_mma<<<gg, 512, SMEM_G>>>(q, k, v, bv, nullptr, 2);

    attn<<<BATCH * HEADS, 256, smemA>>>(mask);

    gemm_mma<<<gg, 512, SMEM_G>>>(q, k, v, bp, out, 3);
}

// round 7
// speedup vs baseline: 2.9893x; 1.0056x over previous
#include <cuda_runtime.h>
#include <cuda_bf16.h>
#include <cstdint>

#define DIMC   512
#define HEADS  8
#define HD     64
#define NTOK   64
#define BATCH  2048
#define MROWS  (BATCH * NTOK)     // 131072
#define SCALE_Q 0.125f
#define PAD    68

// ---------------- device scratch ----------------
__device__ float g_y[(size_t)3 * MROWS * DIMC];                    // Qh|Kh|Vh
__device__ float g_x[(size_t)MROWS * DIMC];                        // attn out
__device__ __align__(128) __nv_bfloat16 g_wblob[(size_t)8 * 512 * 512]; // [g*2+part][n][k]

// ---------------------------------------------------------------------------
// Kernel 0: weights -> hi/lo bf16 blobs, [n][k] row-major.
// ---------------------------------------------------------------------------
__global__ void conv_w(const float* __restrict__ Wq, const float* __restrict__ Wk,
                       const float* __restrict__ Wv, const float* __restrict__ Wp) {
    int idx = blockIdx.x * 256 + threadIdx.x;
    int g   = idx >> 18;
    int rem = idx & 262143;
    const float* W = (g == 0) ? Wq : (g == 1) ? Wk : (g == 2) ? Wv : Wp;
    float w = W[rem];
    __nv_bfloat16 hi = __float2bfloat16(w);
    __nv_bfloat16 lo = __float2bfloat16(w - __bfloat162float(hi));
    g_wblob[(size_t)(g * 2 + 0) * 262144 + rem] = hi;
    g_wblob[(size_t)(g * 2 + 1) * 262144 + rem] = lo;
}

// ---------------------------------------------------------------------------
// GEMM: C[131072,512] = A @ W^T + bias. bf16 hi/lo 3-product mma.sync.
// CTA 128m x 256n, 512 threads = 16 warps (4m x 4n), warp tile 32x64.
// K chunks of 32, 3-stage cp.async pipeline, ldmatrix fragments.
// Compute is organized in 3 dependency-free passes over the 16 accumulators.
// ---------------------------------------------------------------------------
#define KC      32
#define SAK     40
#define OFF_AH  0
#define OFF_AL  (128 * SAK)
#define OFF_BH  (2 * 128 * SAK)
#define OFF_BL  (2 * 128 * SAK + 256 * SAK)
#define STAGE_E (2 * 128 * SAK + 2 * 256 * SAK)   // 30720 bf16 elems
#define SMEM_G  (3 * STAGE_E * 2)                  // 184320 bytes

__device__ __forceinline__ void mma16816(float* d, const uint32_t* a, const uint32_t* b) {
    asm volatile(
        "mma.sync.aligned.m16n8k16.row.col.f32.bf16.bf16.f32 "
        "{%0,%1,%2,%3}, {%4,%5,%6,%7}, {%8,%9}, {%0,%1,%2,%3};"
        : "+f"(d[0]), "+f"(d[1]), "+f"(d[2]), "+f"(d[3])
        : "r"(a[0]), "r"(a[1]), "r"(a[2]), "r"(a[3]), "r"(b[0]), "r"(b[1]));
}
__device__ __forceinline__ void ldsm_x4(uint32_t* r, uint32_t addr) {
    asm volatile("ldmatrix.sync.aligned.m8n8.x4.shared.b16 {%0,%1,%2,%3}, [%4];"
        : "=r"(r[0]), "=r"(r[1]), "=r"(r[2]), "=r"(r[3]) : "r"(addr));
}
__device__ __forceinline__ void cp16(uint32_t dst, const void* src) {
    asm volatile("cp.async.cg.shared.global [%0], [%1], 16;" :: "r"(dst), "l"(src));
}
__device__ __forceinline__ uint32_t pack_bf(__nv_bfloat16 a, __nv_bfloat16 b) {
    return (uint32_t)__bfloat16_as_ushort(a) | ((uint32_t)__bfloat16_as_ushort(b) << 16);
}

__global__ __launch_bounds__(512, 1)
void gemm_mma(const float* __restrict__ qin, const float* __restrict__ kin,
              const float* __restrict__ vin, const float* __restrict__ bias,
              float* __restrict__ Cext, int g) {
    extern __shared__ __nv_bfloat16 sm[];
    const uint32_t sb = (uint32_t)__cvta_generic_to_shared(sm);

    const float* A = (g == 0) ? qin : (g == 1) ? kin : (g == 2) ? vin : (const float*)g_x;
    float* C = (g < 3) ? (g_y + (size_t)g * MROWS * DIMC) : Cext;
    const __nv_bfloat16* Wh = g_wblob + (size_t)(g * 2 + 0) * 262144;
    const __nv_bfloat16* Wl = g_wblob + (size_t)(g * 2 + 1) * 262144;

    const int tid  = threadIdx.x;
    const int lane = tid & 31;
    const int wid  = tid >> 5;
    const int wm   = (wid >> 2) * 32;
    const int wn   = (wid & 3) * 64;
    const int n0   = blockIdx.x * 256;
    const int m0   = blockIdx.y * 128;

    const int arow  = tid >> 2;
    const int acolf = (tid & 3) * 8;
    const int bpart = tid >> 8;
    const int brow  = tid & 255;

    const int a_lrow = (lane & 15);
    const int a_lcol = (lane >> 4) * 8;
    const int b_lrow = ((lane >> 4) << 3) + (lane & 7);
    const int b_lcol = ((lane >> 3) & 1) * 8;

    float acc[2][8][4];
    #pragma unroll
    for (int i = 0; i < 2; i++)
        #pragma unroll
        for (int j = 0; j < 8; j++)
            #pragma unroll
            for (int r = 0; r < 4; r++) acc[i][j][r] = 0.f;

    float4 rA[2];

    auto stageB = [&](int c, int st) {
        uint32_t dst = sb + (uint32_t)(st * STAGE_E +
                       (bpart ? OFF_BL : OFF_BH) + brow * SAK) * 2;
        const __nv_bfloat16* src = (bpart ? Wl : Wh) + (size_t)(n0 + brow) * DIMC + c * KC;
        #pragma unroll
        for (int u = 0; u < 4; u++) cp16(dst + u * 16, src + u * 8);
    };
    auto ldgA = [&](int c) {
        const float* src = A + (size_t)(m0 + arow) * DIMC + c * KC + acolf;
        rA[0] = __ldg((const float4*)src);
        rA[1] = __ldg((const float4*)(src + 4));
    };
    auto stsA = [&](int st) {
        __nv_bfloat16* sAh = sm + st * STAGE_E + OFF_AH + arow * SAK + acolf;
        __nv_bfloat16* sAl = sm + st * STAGE_E + OFF_AL + arow * SAK + acolf;
        #pragma unroll
        for (int u = 0; u < 2; u++) {
            float4 f = rA[u];
            __nv_bfloat16 h0 = __float2bfloat16(f.x), h1 = __float2bfloat16(f.y),
                          h2 = __float2bfloat16(f.z), h3 = __float2bfloat16(f.w);
            __nv_bfloat16 l0 = __float2bfloat16(f.x - __bfloat162float(h0));
            __nv_bfloat16 l1 = __float2bfloat16(f.y - __bfloat162float(h1));
            __nv_bfloat16 l2 = __float2bfloat16(f.z - __bfloat162float(h2));
            __nv_bfloat16 l3 = __float2bfloat16(f.w - __bfloat162float(h3));
            *(uint2*)(sAh + u * 4) = make_uint2(pack_bf(h0, h1), pack_bf(h2, h3));
            *(uint2*)(sAl + u * 4) = make_uint2(pack_bf(l0, l1), pack_bf(l2, l3));
        }
    };
    auto compute = [&](int st) {
        const uint32_t abase = sb + (uint32_t)(st * STAGE_E) * 2;
        #pragma unroll
        for (int ks = 0; ks < 2; ks++) {
            const int kc0 = ks * 16;
            uint32_t bf[8][2];
            uint32_t ah[2][4], al[2][4];
            // A fragments (hi and lo)
            #pragma unroll
            for (int i = 0; i < 2; i++) {
                uint32_t aaddr = abase + (uint32_t)(OFF_AH +
                    (wm + i * 16 + a_lrow) * SAK + kc0 + a_lcol) * 2;
                ldsm_x4(ah[i], aaddr);
                ldsm_x4(al[i], aaddr + (uint32_t)(OFF_AL - OFF_AH) * 2);
            }
            // B-hi fragments
            #pragma unroll
            for (int gg = 0; gg < 4; gg++) {
                uint32_t r[4];
                uint32_t addr = abase + (uint32_t)(OFF_BH +
                    (wn + gg * 16 + b_lrow) * SAK + kc0 + b_lcol) * 2;
                ldsm_x4(r, addr);
                bf[2 * gg][0] = r[0]; bf[2 * gg][1] = r[1];
                bf[2 * gg + 1][0] = r[2]; bf[2 * gg + 1][1] = r[3];
            }
            // pass 1: hi*hi — 16 independent MMAs
            #pragma unroll
            for (int i = 0; i < 2; i++)
                #pragma unroll
                for (int j = 0; j < 8; j++)
                    mma16816(acc[i][j], ah[i], bf[j]);
            // pass 2: lo*hi — acc reuse distance 16
            #pragma unroll
            for (int i = 0; i < 2; i++)
                #pragma unroll
                for (int j = 0; j < 8; j++)
                    mma16816(acc[i][j], al[i], bf[j]);
            // B-lo fragments (bh registers now dead)
            #pragma unroll
            for (int gg = 0; gg < 4; gg++) {
                uint32_t r[4];
                uint32_t addr = abase + (uint32_t)(OFF_BL +
                    (wn + gg * 16 + b_lrow) * SAK + kc0 + b_lcol) * 2;
                ldsm_x4(r, addr);
                bf[2 * gg][0] = r[0]; bf[2 * gg][1] = r[1];
                bf[2 * gg + 1][0] = r[2]; bf[2 * gg + 1][1] = r[3];
            }
            // pass 3: hi*lo
            #pragma unroll
            for (int i = 0; i < 2; i++)
                #pragma unroll
                for (int j = 0; j < 8; j++)
                    mma16816(acc[i][j], ah[i], bf[j]);
        }
    };

    // ---- prologue ----
    stageB(0, 0);
    asm volatile("cp.async.commit_group;" ::: "memory");
    ldgA(0);
    stsA(0);

    // ---- main pipeline ----
    for (int c = 0; c < 16; c++) {
        const int st  = c % 3;
        const int stn = (c + 1) % 3;
        if (c < 15) {
            ldgA(c + 1);
            stageB(c + 1, stn);
            asm volatile("cp.async.commit_group;" ::: "memory");
            asm volatile("cp.async.wait_group 1;" ::: "memory");
        } else {
            asm volatile("cp.async.wait_group 0;" ::: "memory");
        }
        __syncthreads();
        compute(st);
        if (c < 15) stsA(stn);
    }

    // ---- epilogue ----
    #pragma unroll
    for (int j = 0; j < 8; j++) {
        int col = n0 + wn + j * 8 + (lane & 3) * 2;
        float b0 = __ldg(bias + col), b1 = __ldg(bias + col + 1);
        #pragma unroll
        for (int i = 0; i < 2; i++) {
            int row = m0 + wm + i * 16 + (lane >> 2);
            *(float2*)(C + (size_t)row * DIMC + col) =
                make_float2(acc[i][j][0] + b0, acc[i][j][1] + b1);
            *(float2*)(C + (size_t)(row + 8) * DIMC + col) =
                make_float2(acc[i][j][2] + b0, acc[i][j][3] + b1);
        }
    }
}

// ---------------------------------------------------------------------------
// Attention per (b,h) — fp32 in SMEM, reads Qh/Kh/Vh from g_y, writes g_x.
// ---------------------------------------------------------------------------
__global__ __launch_bounds__(256, 2)
void attn(const int* __restrict__ mask) {
    extern __shared__ float smf[];
    float* sQT = smf;
    float* sKT = smf + 1 * 64 * PAD;
    float* sV  = smf + 2 * 64 * PAD;
    float* sS  = smf + 3 * 64 * PAD;
    int* smask = (int*)(smf + 4 * 64 * PAD);

    const int blk = blockIdx.x;
    const int h   = blk & (HEADS - 1);
    const int b   = blk >> 3;
    const int tid = threadIdx.x;
    const int tx  = tid & 15;
    const int ty  = tid >> 4;

    const float* Yq = g_y;
    const float* Yk = g_y + (size_t)1 * MROWS * DIMC;
    const float* Yv = g_y + (size_t)2 * MROWS * DIMC;

    if (tid < NTOK) smask[tid] = mask[b * NTOK + tid];
    #pragma unroll
    for (int it = 0; it < 16; it++) {
        int e = tid + it * 256;
        int i = e >> 6, d = e & 63;
        size_t off = (size_t)(b * 64 + i) * 512 + h * 64 + d;
        sQT[d * PAD + i] = Yq[off] * SCALE_Q;
        sKT[d * PAD + i] = Yk[off];
        sV[i * PAD + d]  = Yv[off];
    }
    __syncthreads();

    {
        float acc[4][4] = {};
        #pragma unroll 16
        for (int d = 0; d < 64; d++) {
            const float4 k4 = *(const float4*)(sKT + d * PAD + (ty << 2));
            const float4 q4 = *(const float4*)(sQT + d * PAD + (tx << 2));
            float kk[4] = {k4.x, k4.y, k4.z, k4.w};
            float qq[4] = {q4.x, q4.y, q4.z, q4.w};
            #pragma unroll
            for (int jj = 0; jj < 4; jj++)
                #pragma unroll
                for (int ii = 0; ii < 4; ii++)
                    acc[jj][ii] = fmaf(kk[jj], qq[ii], acc[jj][ii]);
        }
        #pragma unroll
        for (int jj = 0; jj < 4; jj++) {
            int j = (ty << 2) + jj;
            bool keep = (smask[j] != 0);
            #pragma unroll
            for (int ii = 0; ii < 4; ii++)
                sS[j * PAD + (tx << 2) + ii] = keep ? acc[jj][ii] : -10000.0f;
        }
    }
    __syncthreads();

    {
        int row = tid >> 2;
        int p   = tid & 3;
        float vreg[16];
        float m = -1e30f;
        #pragma unroll
        for (int s = 0; s < 16; s++) {
            vreg[s] = sS[(p * 16 + s) * PAD + row];
            m = fmaxf(m, vreg[s]);
        }
        m = fmaxf(m, __shfl_xor_sync(0xffffffffu, m, 1));
        m = fmaxf(m, __shfl_xor_sync(0xffffffffu, m, 2));
        float sum = 0.f;
        #pragma unroll
        for (int s = 0; s < 16; s++) { vreg[s] = __expf(vreg[s] - m); sum += vreg[s]; }
        sum += __shfl_xor_sync(0xffffffffu, sum, 1);
        sum += __shfl_xor_sync(0xffffffffu, sum, 2);
        float inv = 1.0f / sum;
        #pragma unroll
        for (int s = 0; s < 16; s++) sS[(p * 16 + s) * PAD + row] = vreg[s] * inv;
    }
    __syncthreads();

    {
        float acc[4][4] = {};
        #pragma unroll 16
        for (int j = 0; j < 64; j++) {
            const float4 p4 = *(const float4*)(sS + j * PAD + (ty << 2));
            const float4 v4 = *(const float4*)(sV + j * PAD + (tx << 2));
            float pp[4] = {p4.x, p4.y, p4.z, p4.w};
            float vv[4] = {v4.x, v4.y, v4.z, v4.w};
            #pragma unroll
            for (int ii = 0; ii < 4; ii++)
                #pragma unroll
                for (int dd = 0; dd < 4; dd++)
                    acc[ii][dd] = fmaf(pp[ii], vv[dd], acc[ii][dd]);
        }
        #pragma unroll
        for (int ii = 0; ii < 4; ii++) {
            float4 o = make_float4(acc[ii][0], acc[ii][1], acc[ii][2], acc[ii][3]);
            size_t off = ((size_t)b * NTOK + (ty << 2) + ii) * DIMC + h * HD + (tx << 2);
            *(float4*)(g_x + off) = o;
        }
    }
}

// ---------------------------------------------------------------------------
extern "C" void kernel_launch(void* const* d_in, const int* in_sizes, int n_in,
                              void* d_out, int out_size) {
    const float* q    = (const float*)d_in[0];
    const float* k    = (const float*)d_in[1];
    const float* v    = (const float*)d_in[2];
    const int*   mask = (const int*)  d_in[3];
    const float* Wq   = (const float*)d_in[4];
    const float* bq   = (const float*)d_in[5];
    const float* Wk   = (const float*)d_in[6];
    const float* bk   = (const float*)d_in[7];
    const float* Wv   = (const float*)d_in[8];
    const float* bv   = (const float*)d_in[9];
    const float* Wp   = (const float*)d_in[10];
    const float* bp   = (const float*)d_in[11];
    float* out = (float*)d_out;

    const int smemA = 4 * 64 * PAD * (int)sizeof(float) + NTOK * (int)sizeof(int);
    cudaFuncSetAttribute(gemm_mma, cudaFuncAttributeMaxDynamicSharedMemorySize, SMEM_G);
    cudaFuncSetAttribute(attn, cudaFuncAttributeMaxDynamicSharedMemorySize, smemA);

    conv_w<<<4096, 256>>>(Wq, Wk, Wv, Wp);

    dim3 gg(DIMC / 256, MROWS / 128);
    gemm_mma<<<gg, 512, SMEM_G>>>(q, k, v, bq, nullptr, 0);
    gemm_mma<<<gg, 512, SMEM_G>>>(q, k, v, bk, nullptr, 1);
    gemm_mma<<<gg, 512, SMEM_G>>>(q, k, v, bv, nullptr, 2);

    attn<<<BATCH * HEADS, 256, smemA>>>(mask);

    gemm_mma<<<gg, 512, SMEM_G>>>(q, k, v, bp, out, 3);
}